// round 14
// baseline (speedup 1.0000x reference)
#include <cuda_runtime.h>
#include <cuda_fp16.h>
#include <math.h>
#include <stdint.h>

// ---------------- static config ----------------
#define BB      16
#define CC      512
#define HEADS   16
#define SHIFT   4
#define HID     2048
#define MTOK    (BB*64*64)   // 65536
#define SCALE_F 0.17677669529663687f
#define EPSF    1e-5f

// ---------------- scratch ----------------
__device__ __half g_hwin[(size_t)MTOK * CC];
__device__ __half g_qkv [(size_t)MTOK * 3 * CC];
__device__ __half g_o   [(size_t)MTOK * CC];
__device__ float  g_x1  [(size_t)MTOK * CC];
__device__ __half g_h2n [(size_t)MTOK * CC];
__device__ __half g_hid [(size_t)MTOK * HID];
__device__ __half g_wq  [3*CC*CC];
__device__ __half g_wp  [CC*CC];
__device__ __half g_w1  [HID*CC];
__device__ __half g_w2  [CC*HID];
__device__ float  g_bm  [(size_t)1024 * 4096];

// ---------------- helpers ----------------
__device__ __forceinline__ uint32_t s2u(const void* p) {
    uint32_t a;
    asm("{ .reg .u64 t; cvta.to.shared.u64 t, %1; cvt.u32.u64 %0, t; }" : "=r"(a) : "l"(p));
    return a;
}
#define CP16(s, g) \
    asm volatile("cp.async.cg.shared.global [%0], [%1], 16;" :: "r"(s), "l"(g))
#define CP_COMMIT() asm volatile("cp.async.commit_group;" ::: "memory")
#define CP_WAIT(N)  asm volatile("cp.async.wait_group %0;" :: "n"(N) : "memory")

#define LDSM4(r, a) \
    asm volatile("ldmatrix.sync.aligned.m8n8.x4.shared.b16 {%0,%1,%2,%3}, [%4];" \
        : "=r"((r)[0]), "=r"((r)[1]), "=r"((r)[2]), "=r"((r)[3]) : "r"(a))
#define LDSM4T(r, a) \
    asm volatile("ldmatrix.sync.aligned.m8n8.x4.trans.shared.b16 {%0,%1,%2,%3}, [%4];" \
        : "=r"((r)[0]), "=r"((r)[1]), "=r"((r)[2]), "=r"((r)[3]) : "r"(a))

__device__ __forceinline__ void mma_f16(float* c, const uint32_t* a, const uint32_t* b) {
    asm volatile(
        "mma.sync.aligned.m16n8k16.row.col.f32.f16.f16.f32 "
        "{%0,%1,%2,%3}, {%4,%5,%6,%7}, {%8,%9}, {%0,%1,%2,%3};"
        : "+f"(c[0]), "+f"(c[1]), "+f"(c[2]), "+f"(c[3])
        : "r"(a[0]), "r"(a[1]), "r"(a[2]), "r"(a[3]), "r"(b[0]), "r"(b[1]));
}

__device__ __forceinline__ uint32_t pkh2(float a, float b) {
    __half2 t = __floats2half2_rn(a, b);
    return *reinterpret_cast<uint32_t*>(&t);
}

__device__ __forceinline__ size_t scatter_base(int m) {
    int bb = m >> 12, rem = m & 4095;
    int wdx = rem >> 6, n = rem & 63;
    int wh = wdx >> 3, ww = wdx & 7;
    int r = n >> 3, s = n & 7;
    int hp = ((wh << 3) + r + SHIFT) & 63;
    int wp = ((ww << 3) + s + SHIFT) & 63;
    return ((size_t)bb * 4096 + hp * 64 + wp) * CC;
}

// ---------------- fused weight conversion fp32 -> fp16 ----------------
__global__ void cvtw_all(const float* __restrict__ qkv_w, const float* __restrict__ proj_w,
                         const float* __restrict__ fc1_w, const float* __restrict__ fc2_w,
                         __half* __restrict__ wq, __half* __restrict__ wp,
                         __half* __restrict__ w1, __half* __restrict__ w2)
{
    int i = blockIdx.x * 256 + threadIdx.x;
    const float* src; __half* dst; int off;
    if (i < 196608)       { src = qkv_w;  dst = wq; off = i; }
    else if (i < 262144)  { src = proj_w; dst = wp; off = i - 196608; }
    else if (i < 524288)  { src = fc1_w;  dst = w1; off = i - 262144; }
    else                  { src = fc2_w;  dst = w2; off = i - 524288; }
    float4 v = ((const float4*)src)[off];
    __half2 a = __floats2half2_rn(v.x, v.y);
    __half2 b = __floats2half2_rn(v.z, v.w);
    uint2 pk = { *(uint32_t*)&a, *(uint32_t*)&b };
    ((uint2*)dst)[off] = pk;
}

// ---------------- bias+mask precompute ----------------
__global__ void bmprep(const float* __restrict__ mask,
                       const float* __restrict__ rbt,
                       const int*   __restrict__ rpi,
                       float* __restrict__ bm)
{
    int hw   = blockIdx.x;
    int head = hw >> 6, wim = hw & 63;
    const float* mrow = mask + wim * 4096;
    float* dst = bm + (size_t)hw * 4096;
    for (int e = threadIdx.x; e < 4096; e += 256)
        dst[e] = mrow[e] + rbt[rpi[e] * HEADS + head];
}

// ---------------- LayerNorm (+shift/window gather), fp16 out ---------------
template<bool SHIFTED>
__global__ void ln_kernel(const float* __restrict__ x,
                          const float* __restrict__ w,
                          const float* __restrict__ b,
                          __half* __restrict__ out)
{
    __shared__ float sh[4];
    int m   = blockIdx.x;
    int tid = threadIdx.x;          // 128

    size_t dst_row = (size_t)m * CC;
    size_t src_row = dst_row;
    if (SHIFTED) {
        int bb  = m >> 12;
        int rem = m & 4095;
        int wdx = rem >> 6, n = rem & 63;
        int wh = wdx >> 3, ww = wdx & 7;
        int r  = n >> 3, s = n & 7;
        int shp = ((wh << 3) + r + SHIFT) & 63;
        int swp = ((ww << 3) + s + SHIFT) & 63;
        src_row = ((size_t)bb * 4096 + shp * 64 + swp) * CC;
    }

    float4 v = ((const float4*)(x + src_row))[tid];

    float sum = v.x + v.y + v.z + v.w;
    #pragma unroll
    for (int o = 16; o > 0; o >>= 1) sum += __shfl_xor_sync(0xffffffffu, sum, o);
    if ((tid & 31) == 0) sh[tid >> 5] = sum;
    __syncthreads();
    float mean = (sh[0] + sh[1] + sh[2] + sh[3]) * (1.0f / CC);
    __syncthreads();

    float d0 = v.x - mean, d1 = v.y - mean, d2 = v.z - mean, d3 = v.w - mean;
    float sq = d0*d0 + d1*d1 + d2*d2 + d3*d3;
    #pragma unroll
    for (int o = 16; o > 0; o >>= 1) sq += __shfl_xor_sync(0xffffffffu, sq, o);
    if ((tid & 31) == 0) sh[tid >> 5] = sq;
    __syncthreads();
    float var = (sh[0] + sh[1] + sh[2] + sh[3]) * (1.0f / CC);
    float inv = rsqrtf(var + EPSF);

    float4 w4 = ((const float4*)w)[tid];
    float4 b4 = ((const float4*)b)[tid];
    __half2 h01 = __floats2half2_rn(d0 * inv * w4.x + b4.x, d1 * inv * w4.y + b4.y);
    __half2 h23 = __floats2half2_rn(d2 * inv * w4.z + b4.z, d3 * inv * w4.w + b4.w);
    uint2 pk = { *(uint32_t*)&h01, *(uint32_t*)&h23 };
    *(uint2*)(out + dst_row + tid * 4) = pk;
}

// ---------------- fp16 HMMA GEMM, 256 thr, block 64x128, warp 32x32 --------
#define EPI_PLAIN       0
#define EPI_GELU        1
#define EPI_SCATTER_RES 2
#define EPI_RES         3

// stage: A 64 rows x 80B (5120) + B 128 rows x 80B (10240) = 15360 B; 3 stages
#define HSTAGE    15360
#define HSM_TOTAL 46080

__device__ __forceinline__ void cp_stage3(uint32_t sb, int st, int tid,
                                          const __half* pa, const __half* pb) {
    // A: thread t -> row t>>2, 16B-col t&3   (1 op)
    // B: thread t -> row t>>1, 16B-cols (t&1)*2 + {0,1}  (2 ops)
    const uint32_t stA = sb + st * HSTAGE;
    const uint32_t stB = stA + 5120;
    const int arow = tid >> 2, acol = tid & 3;
    const int brow = tid >> 1, bcol = (tid & 1) * 2;
    CP16(stA + arow * 80 + acol * 16, pa);
    CP16(stB + brow * 80 + bcol * 16,      pb);
    CP16(stB + brow * 80 + bcol * 16 + 16, pb + 8);
    CP_COMMIT();
}

template<int EPI>
__global__ __launch_bounds__(256, 3)
void h_gemm(const __half* __restrict__ A,
            const __half* __restrict__ Bw,
            const float* __restrict__ bias,
            float* __restrict__ outf,
            __half* __restrict__ outh,
            int Nc, int K,
            const float* __restrict__ Res)
{
    extern __shared__ char smem[];

    const int tid  = threadIdx.x;     // 256
    const int lane = tid & 31;
    const int w    = tid >> 5;        // 8 warps
    const int wr   = (w & 1)  * 32;   // 2 M-strips of 32
    const int wc   = (w >> 1) * 32;   // 4 N-strips of 32
    const int bm   = blockIdx.y * 64;
    const int bn   = blockIdx.x * 128;

    const uint32_t sb = s2u(smem);

    // loader pointers
    const int arow = tid >> 2, acol = tid & 3;
    const int brow = tid >> 1, bcol = (tid & 1) * 2;
    const __half* gA = A  + (size_t)(bm + arow) * K + acol * 8;
    const __half* gB = Bw + (size_t)(bn + brow) * K + bcol * 8;

    float acc[2][4][4];
    #pragma unroll
    for (int i = 0; i < 2; i++)
        #pragma unroll
        for (int j = 0; j < 4; j++)
            #pragma unroll
            for (int q = 0; q < 4; q++) acc[i][j][q] = 0.f;

    const int nch = K >> 5;           // K/32 chunks

    const int tile = lane >> 3, rit = lane & 7;
    uint32_t aOff[2], bOff[2];
    #pragma unroll
    for (int mb = 0; mb < 2; mb++)
        aOff[mb] = (uint32_t)((wr + mb * 16 + (tile & 1) * 8 + rit) * 80 + (tile >> 1) * 16);
    #pragma unroll
    for (int p = 0; p < 2; p++)
        bOff[p] = (uint32_t)(5120 + (wc + p * 16 + (tile >> 1) * 8 + rit) * 80 + (tile & 1) * 16);

    cp_stage3(sb, 0, tid, gA,      gB);
    cp_stage3(sb, 1, tid, gA + 32, gB + 32);

    int st_ld = 2;
    for (int c = 0; c < nch; c++) {
        CP_WAIT(1);
        __syncthreads();
        if (c + 2 < nch) {
            cp_stage3(sb, st_ld, tid, gA + (c + 2) * 32, gB + (c + 2) * 32);
        }
        const uint32_t stb = sb + (uint32_t)(c % 3) * HSTAGE;
        #pragma unroll
        for (int kk = 0; kk < 2; kk++) {
            uint32_t a[2][4], b[2][4];
            #pragma unroll
            for (int mb = 0; mb < 2; mb++) LDSM4(a[mb], stb + aOff[mb] + kk * 32);
            #pragma unroll
            for (int p = 0; p < 2; p++)    LDSM4(b[p],  stb + bOff[p] + kk * 32);
            #pragma unroll
            for (int mb = 0; mb < 2; mb++)
                #pragma unroll
                for (int nb = 0; nb < 4; nb++)
                    mma_f16(acc[mb][nb], a[mb], &b[nb >> 1][(nb & 1) * 2]);
        }
        st_ld = (st_ld == 2) ? 0 : st_ld + 1;
    }

    const int fr = lane >> 2, fc = lane & 3;
    #pragma unroll
    for (int mb = 0; mb < 2; mb++) {
        const int m0 = bm + wr + mb * 16 + fr;
        const int m1 = m0 + 8;
        size_t ob0, ob1;
        if (EPI == EPI_SCATTER_RES) { ob0 = scatter_base(m0); ob1 = scatter_base(m1); }
        else                        { ob0 = (size_t)m0 * Nc;  ob1 = (size_t)m1 * Nc; }
        #pragma unroll
        for (int nb = 0; nb < 4; nb++) {
            const int n0 = bn + wc + nb * 8 + 2 * fc;
            float2 bb = *(const float2*)(bias + n0);
            float v0 = acc[mb][nb][0] + bb.x;
            float v1 = acc[mb][nb][1] + bb.y;
            float v2 = acc[mb][nb][2] + bb.x;
            float v3 = acc[mb][nb][3] + bb.y;
            if (EPI == EPI_GELU) {
                v0 = 0.5f * v0 * (1.0f + erff(v0 * 0.70710678118654752f));
                v1 = 0.5f * v1 * (1.0f + erff(v1 * 0.70710678118654752f));
                v2 = 0.5f * v2 * (1.0f + erff(v2 * 0.70710678118654752f));
                v3 = 0.5f * v3 * (1.0f + erff(v3 * 0.70710678118654752f));
            } else if (EPI == EPI_SCATTER_RES || EPI == EPI_RES) {
                float2 r0 = *(const float2*)(Res + ob0 + n0);
                float2 r1 = *(const float2*)(Res + ob1 + n0);
                v0 += r0.x; v1 += r0.y; v2 += r1.x; v3 += r1.y;
            }
            if (EPI == EPI_PLAIN || EPI == EPI_GELU) {
                *(uint32_t*)(outh + ob0 + n0) = pkh2(v0, v1);
                *(uint32_t*)(outh + ob1 + n0) = pkh2(v2, v3);
            } else {
                *(float2*)(outf + ob0 + n0) = make_float2(v0, v1);
                *(float2*)(outf + ob1 + n0) = make_float2(v2, v3);
            }
        }
    }
}

// ---------------- HMMA windowed attention ----------------------------------
#define BMS 68

__global__ __launch_bounds__(128)
void attn_mma(const __half* __restrict__ qkv,
              const float* __restrict__ bm,
              __half* __restrict__ outp)
{
    int head = blockIdx.x;
    int bw   = blockIdx.y;
    int wim  = bw & 63;
    int tid  = threadIdx.x;
    int lane = tid & 31;
    int w    = tid >> 5;
    int wr   = w * 16;

    __shared__ __half sQ[64*40], sK[64*40], sV[64*40];
    __shared__ float  sBM[64*BMS];

    size_t rowbase = (size_t)(bw * 64) * 1536 + head * 32;
    for (int i = tid; i < 256; i += 128) {
        int n = i >> 2, c = i & 3;
        const __half* src = qkv + rowbase + (size_t)n * 1536 + c * 8;
        *(uint4*)(sQ + n * 40 + c * 8) = *(const uint4*)src;
        *(uint4*)(sK + n * 40 + c * 8) = *(const uint4*)(src + 512);
        *(uint4*)(sV + n * 40 + c * 8) = *(const uint4*)(src + 1024);
    }
    {
        const float4* src = (const float4*)(bm + ((size_t)head * 64 + wim) * 4096);
        for (int e = tid; e < 1024; e += 128) {
            int n = e >> 4, c = e & 15;
            *(float4*)(sBM + n * BMS + c * 4) = src[e];
        }
    }
    __syncthreads();

    const uint32_t uQ = s2u(sQ), uK = s2u(sK), uV = s2u(sV);
    const int tile = lane >> 3, rit = lane & 7;
    const int fr = lane >> 2, fc = lane & 3;

    uint32_t aQ[2][4];
    #pragma unroll
    for (int kt = 0; kt < 2; kt++)
        LDSM4(aQ[kt], uQ + (uint32_t)(((wr + (tile & 1) * 8 + rit) * 40
                                       + (tile >> 1) * 8 + kt * 16) * 2));

    uint32_t bK[4][2][4];
    #pragma unroll
    for (int pt = 0; pt < 4; pt++)
        #pragma unroll
        for (int kt = 0; kt < 2; kt++)
            LDSM4(bK[pt][kt], uK + (uint32_t)(((pt * 16 + (tile >> 1) * 8 + rit) * 40
                                               + (tile & 1) * 8 + kt * 16) * 2));

    float c[8][4];
    #pragma unroll
    for (int i = 0; i < 8; i++)
        #pragma unroll
        for (int j = 0; j < 4; j++) c[i][j] = 0.f;
    #pragma unroll
    for (int pt = 0; pt < 4; pt++)
        #pragma unroll
        for (int kt = 0; kt < 2; kt++) {
            mma_f16(c[2 * pt],     aQ[kt], &bK[pt][kt][0]);
            mma_f16(c[2 * pt + 1], aQ[kt], &bK[pt][kt][2]);
        }

    const float* bm0 = sBM + (wr + fr) * BMS;
    const float* bm1 = bm0 + 8 * BMS;
    float mx0 = -1e30f, mx1 = -1e30f;
    #pragma unroll
    for (int nt = 0; nt < 8; nt++) {
        float2 b0 = *(const float2*)(bm0 + nt * 8 + 2 * fc);
        float2 b1 = *(const float2*)(bm1 + nt * 8 + 2 * fc);
        c[nt][0] = c[nt][0] * SCALE_F + b0.x;
        c[nt][1] = c[nt][1] * SCALE_F + b0.y;
        c[nt][2] = c[nt][2] * SCALE_F + b1.x;
        c[nt][3] = c[nt][3] * SCALE_F + b1.y;
        mx0 = fmaxf(mx0, fmaxf(c[nt][0], c[nt][1]));
        mx1 = fmaxf(mx1, fmaxf(c[nt][2], c[nt][3]));
    }
    mx0 = fmaxf(mx0, __shfl_xor_sync(0xffffffffu, mx0, 1));
    mx0 = fmaxf(mx0, __shfl_xor_sync(0xffffffffu, mx0, 2));
    mx1 = fmaxf(mx1, __shfl_xor_sync(0xffffffffu, mx1, 1));
    mx1 = fmaxf(mx1, __shfl_xor_sync(0xffffffffu, mx1, 2));

    float s0 = 0.f, s1 = 0.f;
    #pragma unroll
    for (int nt = 0; nt < 8; nt++) {
        c[nt][0] = __expf(c[nt][0] - mx0);
        c[nt][1] = __expf(c[nt][1] - mx0);
        c[nt][2] = __expf(c[nt][2] - mx1);
        c[nt][3] = __expf(c[nt][3] - mx1);
        s0 += c[nt][0] + c[nt][1];
        s1 += c[nt][2] + c[nt][3];
    }
    s0 += __shfl_xor_sync(0xffffffffu, s0, 1);
    s0 += __shfl_xor_sync(0xffffffffu, s0, 2);
    s1 += __shfl_xor_sync(0xffffffffu, s1, 1);
    s1 += __shfl_xor_sync(0xffffffffu, s1, 2);
    float i0 = 1.0f / s0, i1 = 1.0f / s1;

    uint32_t aP[4][4];
    #pragma unroll
    for (int kt = 0; kt < 4; kt++) {
        aP[kt][0] = pkh2(c[2*kt][0] * i0,   c[2*kt][1] * i0);
        aP[kt][1] = pkh2(c[2*kt][2] * i1,   c[2*kt][3] * i1);
        aP[kt][2] = pkh2(c[2*kt+1][0] * i0, c[2*kt+1][1] * i0);
        aP[kt][3] = pkh2(c[2*kt+1][2] * i1, c[2*kt+1][3] * i1);
    }

    float o[4][4];
    #pragma unroll
    for (int i = 0; i < 4; i++)
        #pragma unroll
        for (int j = 0; j < 4; j++) o[i][j] = 0.f;
    #pragma unroll
    for (int kt = 0; kt < 4; kt++)
        #pragma unroll
        for (int dh = 0; dh < 2; dh++) {
            uint32_t bV[4];
            LDSM4T(bV, uV + (uint32_t)(((kt * 16 + ((lane >> 3) & 1) * 8 + (lane & 7)) * 40
                                        + (lane >> 4) * 8 + dh * 16) * 2));
            mma_f16(o[2 * dh],     aP[kt], &bV[0]);
            mma_f16(o[2 * dh + 1], aP[kt], &bV[2]);
        }

    size_t orow = (size_t)(bw * 64 + wr + fr) * 512 + head * 32;
    #pragma unroll
    for (int nt = 0; nt < 4; nt++) {
        *(uint32_t*)(outp + orow + nt * 8 + 2 * fc)             = pkh2(o[nt][0], o[nt][1]);
        *(uint32_t*)(outp + orow + 8 * 512 + nt * 8 + 2 * fc)   = pkh2(o[nt][2], o[nt][3]);
    }
}

// ---------------- launch ----------------
extern "C" void kernel_launch(void* const* d_in, const int* in_sizes, int n_in,
                              void* d_out, int out_size)
{
    const float* x      = (const float*)d_in[0];
    const float* qkv_w  = (const float*)d_in[1];
    const float* qkv_b  = (const float*)d_in[2];
    const float* proj_w = (const float*)d_in[3];
    const float* proj_b = (const float*)d_in[4];
    const float* n1w    = (const float*)d_in[5];
    const float* n1b    = (const float*)d_in[6];
    const float* n2w    = (const float*)d_in[7];
    const float* n2b    = (const float*)d_in[8];
    const float* fc1w   = (const float*)d_in[9];
    const float* fc1b   = (const float*)d_in[10];
    const float* fc2w   = (const float*)d_in[11];
    const float* fc2b   = (const float*)d_in[12];
    const float* rbt    = (const float*)d_in[13];
    const int*   rpi    = (const int*)d_in[14];
    const float* amask  = (const float*)d_in[15];
    float*       out    = (float*)d_out;

    __half *hwin, *qkvb, *ob, *h2nb, *hidb, *wq, *wp, *w1, *w2;
    float *x1b, *bmb;
    cudaGetSymbolAddress((void**)&hwin, g_hwin);
    cudaGetSymbolAddress((void**)&qkvb, g_qkv);
    cudaGetSymbolAddress((void**)&ob,   g_o);
    cudaGetSymbolAddress((void**)&x1b,  g_x1);
    cudaGetSymbolAddress((void**)&h2nb, g_h2n);
    cudaGetSymbolAddress((void**)&hidb, g_hid);
    cudaGetSymbolAddress((void**)&wq,   g_wq);
    cudaGetSymbolAddress((void**)&wp,   g_wp);
    cudaGetSymbolAddress((void**)&w1,   g_w1);
    cudaGetSymbolAddress((void**)&w2,   g_w2);
    cudaGetSymbolAddress((void**)&bmb,  g_bm);

    cudaFuncSetAttribute(h_gemm<EPI_PLAIN>,       cudaFuncAttributeMaxDynamicSharedMemorySize, HSM_TOTAL);
    cudaFuncSetAttribute(h_gemm<EPI_GELU>,        cudaFuncAttributeMaxDynamicSharedMemorySize, HSM_TOTAL);
    cudaFuncSetAttribute(h_gemm<EPI_SCATTER_RES>, cudaFuncAttributeMaxDynamicSharedMemorySize, HSM_TOTAL);
    cudaFuncSetAttribute(h_gemm<EPI_RES>,         cudaFuncAttributeMaxDynamicSharedMemorySize, HSM_TOTAL);

    cvtw_all<<<786432/256, 256>>>(qkv_w, proj_w, fc1w, fc2w, wq, wp, w1, w2);
    bmprep<<<1024, 256>>>(amask, rbt, rpi, bmb);

    ln_kernel<true><<<MTOK, 128>>>(x, n1w, n1b, hwin);

    h_gemm<EPI_PLAIN><<<dim3(1536/128, MTOK/64), 256, HSM_TOTAL>>>(
        hwin, wq, qkv_b, nullptr, qkvb, 1536, 512, nullptr);

    attn_mma<<<dim3(HEADS, BB*64), 128>>>(qkvb, bmb, ob);

    h_gemm<EPI_SCATTER_RES><<<dim3(512/128, MTOK/64), 256, HSM_TOTAL>>>(
        ob, wp, proj_b, x1b, nullptr, 512, 512, x);

    ln_kernel<false><<<MTOK, 128>>>(x1b, n2w, n2b, h2nb);

    h_gemm<EPI_GELU><<<dim3(2048/128, MTOK/64), 256, HSM_TOTAL>>>(
        h2nb, w1, fc1b, nullptr, hidb, 2048, 512, nullptr);

    h_gemm<EPI_RES><<<dim3(512/128, MTOK/64), 256, HSM_TOTAL>>>(
        hidb, w2, fc2b, out, nullptr, 512, 2048, x1b);
}

// round 15
// speedup vs baseline: 1.1034x; 1.1034x over previous
#include <cuda_runtime.h>
#include <cuda_fp16.h>
#include <math.h>
#include <stdint.h>

// ---------------- static config ----------------
#define BB      16
#define CC      512
#define HEADS   16
#define SHIFT   4
#define HID     2048
#define MTOK    (BB*64*64)   // 65536
#define SCALE_F 0.17677669529663687f
#define EPSF    1e-5f

// ---------------- scratch ----------------
__device__ __half g_hwin[(size_t)MTOK * CC];
__device__ __half g_qkv [(size_t)MTOK * 3 * CC];
__device__ __half g_o   [(size_t)MTOK * CC];
__device__ float  g_x1  [(size_t)MTOK * CC];
__device__ __half g_h2n [(size_t)MTOK * CC];
__device__ __half g_hid [(size_t)MTOK * HID];
__device__ __half g_wq  [3*CC*CC];
__device__ __half g_wp  [CC*CC];
__device__ __half g_w1  [HID*CC];
__device__ __half g_w2  [CC*HID];
__device__ float  g_bm  [(size_t)1024 * 4096];

// ---------------- helpers ----------------
__device__ __forceinline__ uint32_t s2u(const void* p) {
    uint32_t a;
    asm("{ .reg .u64 t; cvta.to.shared.u64 t, %1; cvt.u32.u64 %0, t; }" : "=r"(a) : "l"(p));
    return a;
}
#define CP16(s, g) \
    asm volatile("cp.async.cg.shared.global [%0], [%1], 16;" :: "r"(s), "l"(g))
#define CP_COMMIT() asm volatile("cp.async.commit_group;" ::: "memory")
#define CP_WAIT(N)  asm volatile("cp.async.wait_group %0;" :: "n"(N) : "memory")

#define LDSM4(r, a) \
    asm volatile("ldmatrix.sync.aligned.m8n8.x4.shared.b16 {%0,%1,%2,%3}, [%4];" \
        : "=r"((r)[0]), "=r"((r)[1]), "=r"((r)[2]), "=r"((r)[3]) : "r"(a))
#define LDSM4T(r, a) \
    asm volatile("ldmatrix.sync.aligned.m8n8.x4.trans.shared.b16 {%0,%1,%2,%3}, [%4];" \
        : "=r"((r)[0]), "=r"((r)[1]), "=r"((r)[2]), "=r"((r)[3]) : "r"(a))

__device__ __forceinline__ void mma_f16(float* c, const uint32_t* a, const uint32_t* b) {
    asm volatile(
        "mma.sync.aligned.m16n8k16.row.col.f32.f16.f16.f32 "
        "{%0,%1,%2,%3}, {%4,%5,%6,%7}, {%8,%9}, {%0,%1,%2,%3};"
        : "+f"(c[0]), "+f"(c[1]), "+f"(c[2]), "+f"(c[3])
        : "r"(a[0]), "r"(a[1]), "r"(a[2]), "r"(a[3]), "r"(b[0]), "r"(b[1]));
}

__device__ __forceinline__ uint32_t pkh2(float a, float b) {
    __half2 t = __floats2half2_rn(a, b);
    return *reinterpret_cast<uint32_t*>(&t);
}

__device__ __forceinline__ size_t scatter_base(int m) {
    int bb = m >> 12, rem = m & 4095;
    int wdx = rem >> 6, n = rem & 63;
    int wh = wdx >> 3, ww = wdx & 7;
    int r = n >> 3, s = n & 7;
    int hp = ((wh << 3) + r + SHIFT) & 63;
    int wp = ((ww << 3) + s + SHIFT) & 63;
    return ((size_t)bb * 4096 + hp * 64 + wp) * CC;
}

// ---------------- fused weight conversion fp32 -> fp16 ----------------
__global__ void cvtw_all(const float* __restrict__ qkv_w, const float* __restrict__ proj_w,
                         const float* __restrict__ fc1_w, const float* __restrict__ fc2_w,
                         __half* __restrict__ wq, __half* __restrict__ wp,
                         __half* __restrict__ w1, __half* __restrict__ w2)
{
    int i = blockIdx.x * 256 + threadIdx.x;
    const float* src; __half* dst; int off;
    if (i < 196608)       { src = qkv_w;  dst = wq; off = i; }
    else if (i < 262144)  { src = proj_w; dst = wp; off = i - 196608; }
    else if (i < 524288)  { src = fc1_w;  dst = w1; off = i - 262144; }
    else                  { src = fc2_w;  dst = w2; off = i - 524288; }
    float4 v = ((const float4*)src)[off];
    __half2 a = __floats2half2_rn(v.x, v.y);
    __half2 b = __floats2half2_rn(v.z, v.w);
    uint2 pk = { *(uint32_t*)&a, *(uint32_t*)&b };
    ((uint2*)dst)[off] = pk;
}

// ---------------- bias+mask precompute ----------------
__global__ void bmprep(const float* __restrict__ mask,
                       const float* __restrict__ rbt,
                       const int*   __restrict__ rpi,
                       float* __restrict__ bm)
{
    int hw   = blockIdx.x;
    int head = hw >> 6, wim = hw & 63;
    const float* mrow = mask + wim * 4096;
    float* dst = bm + (size_t)hw * 4096;
    for (int e = threadIdx.x; e < 4096; e += 256)
        dst[e] = mrow[e] + rbt[rpi[e] * HEADS + head];
}

// ---------------- LayerNorm (+shift/window gather), fp16 out ---------------
template<bool SHIFTED>
__global__ void ln_kernel(const float* __restrict__ x,
                          const float* __restrict__ w,
                          const float* __restrict__ b,
                          __half* __restrict__ out)
{
    __shared__ float sh[4];
    int m   = blockIdx.x;
    int tid = threadIdx.x;          // 128

    size_t dst_row = (size_t)m * CC;
    size_t src_row = dst_row;
    if (SHIFTED) {
        int bb  = m >> 12;
        int rem = m & 4095;
        int wdx = rem >> 6, n = rem & 63;
        int wh = wdx >> 3, ww = wdx & 7;
        int r  = n >> 3, s = n & 7;
        int shp = ((wh << 3) + r + SHIFT) & 63;
        int swp = ((ww << 3) + s + SHIFT) & 63;
        src_row = ((size_t)bb * 4096 + shp * 64 + swp) * CC;
    }

    float4 v = ((const float4*)(x + src_row))[tid];

    float sum = v.x + v.y + v.z + v.w;
    #pragma unroll
    for (int o = 16; o > 0; o >>= 1) sum += __shfl_xor_sync(0xffffffffu, sum, o);
    if ((tid & 31) == 0) sh[tid >> 5] = sum;
    __syncthreads();
    float mean = (sh[0] + sh[1] + sh[2] + sh[3]) * (1.0f / CC);
    __syncthreads();

    float d0 = v.x - mean, d1 = v.y - mean, d2 = v.z - mean, d3 = v.w - mean;
    float sq = d0*d0 + d1*d1 + d2*d2 + d3*d3;
    #pragma unroll
    for (int o = 16; o > 0; o >>= 1) sq += __shfl_xor_sync(0xffffffffu, sq, o);
    if ((tid & 31) == 0) sh[tid >> 5] = sq;
    __syncthreads();
    float var = (sh[0] + sh[1] + sh[2] + sh[3]) * (1.0f / CC);
    float inv = rsqrtf(var + EPSF);

    float4 w4 = ((const float4*)w)[tid];
    float4 b4 = ((const float4*)b)[tid];
    __half2 h01 = __floats2half2_rn(d0 * inv * w4.x + b4.x, d1 * inv * w4.y + b4.y);
    __half2 h23 = __floats2half2_rn(d2 * inv * w4.z + b4.z, d3 * inv * w4.w + b4.w);
    uint2 pk = { *(uint32_t*)&h01, *(uint32_t*)&h23 };
    *(uint2*)(out + dst_row + tid * 4) = pk;
}

// ---------------- fp16 HMMA GEMM, 256 thr, 128x128 block, 32x64 warp tile --
// 4-stage ring, processed in chunk PAIRS: 1 wait + 1 barrier per 64 k
#define EPI_PLAIN       0
#define EPI_GELU        1
#define EPI_SCATTER_RES 2
#define EPI_RES         3

#define HSTAGE    20480
#define HSM_TOTAL 81920   // 4 stages

__device__ __forceinline__ void cp_chunk(uint32_t sb, int buf, int tid,
                                         const __half* pa, const __half* pb) {
    const int row = tid >> 1, hf = tid & 1;
    uint32_t da = sb + buf * HSTAGE +         row * 80 + hf * 32;
    uint32_t db = sb + buf * HSTAGE + 10240 + row * 80 + hf * 32;
    CP16(da,      pa);
    CP16(da + 16, pa + 8);
    CP16(db,      pb);
    CP16(db + 16, pb + 8);
}

template<int EPI>
__global__ __launch_bounds__(256, 2)
void h_gemm(const __half* __restrict__ A,
            const __half* __restrict__ Bw,
            const float* __restrict__ bias,
            float* __restrict__ outf,
            __half* __restrict__ outh,
            int Nc, int K,
            const float* __restrict__ Res)
{
    extern __shared__ char smem[];

    const int tid  = threadIdx.x;     // 256
    const int lane = tid & 31;
    const int w    = tid >> 5;        // 8 warps
    const int wr   = (w >> 1) * 32;   // 4 M-strips of 32
    const int wc   = (w & 1)  * 64;   // 2 N-strips of 64
    const int bm   = blockIdx.y * 128;
    const int bn   = blockIdx.x * 128;

    const uint32_t sb = s2u(smem);

    const int lrow = tid >> 1, lhf = tid & 1;
    const __half* gA = A  + (size_t)(bm + lrow) * K + lhf * 16;
    const __half* gB = Bw + (size_t)(bn + lrow) * K + lhf * 16;

    float acc[2][8][4];
    #pragma unroll
    for (int i = 0; i < 2; i++)
        #pragma unroll
        for (int j = 0; j < 8; j++)
            #pragma unroll
            for (int q = 0; q < 4; q++) acc[i][j][q] = 0.f;

    const int npair = K >> 6;         // pairs of 32-chunks

    const int tile = lane >> 3, rit = lane & 7;
    uint32_t aOff[2], bOff[4];
    #pragma unroll
    for (int mb = 0; mb < 2; mb++)
        aOff[mb] = (uint32_t)((wr + mb * 16 + (tile & 1) * 8 + rit) * 80 + (tile >> 1) * 16);
    #pragma unroll
    for (int p = 0; p < 4; p++)
        bOff[p] = (uint32_t)(10240 + (wc + p * 16 + (tile >> 1) * 8 + rit) * 80 + (tile & 1) * 16);

    // prologue: pair 0 -> bufs 0,1
    cp_chunk(sb, 0, tid, gA,      gB);
    cp_chunk(sb, 1, tid, gA + 32, gB + 32);
    CP_COMMIT();

    for (int p = 0; p < npair; p++) {
        CP_WAIT(0);
        __syncthreads();
        const int pb2 = (p & 1) * 2;          // this pair's buffers: pb2, pb2+1
        if (p + 1 < npair) {
            const int nb2 = ((p + 1) & 1) * 2;
            const __half* pa = gA + (size_t)(p + 1) * 64;
            const __half* pbp = gB + (size_t)(p + 1) * 64;
            cp_chunk(sb, nb2,     tid, pa,      pbp);
            cp_chunk(sb, nb2 + 1, tid, pa + 32, pbp + 32);
            CP_COMMIT();
        }
        #pragma unroll
        for (int sub = 0; sub < 2; sub++) {
            const uint32_t stb = sb + (uint32_t)(pb2 + sub) * HSTAGE;
            #pragma unroll
            for (int kk = 0; kk < 2; kk++) {
                uint32_t a[2][4], b[4][4];
                #pragma unroll
                for (int mb = 0; mb < 2; mb++) LDSM4(a[mb], stb + aOff[mb] + kk * 32);
                #pragma unroll
                for (int pt = 0; pt < 4; pt++) LDSM4(b[pt], stb + bOff[pt] + kk * 32);
                #pragma unroll
                for (int mb = 0; mb < 2; mb++)
                    #pragma unroll
                    for (int nb = 0; nb < 8; nb++)
                        mma_f16(acc[mb][nb], a[mb], &b[nb >> 1][(nb & 1) * 2]);
            }
        }
    }

    const int fr = lane >> 2, fc = lane & 3;
    #pragma unroll
    for (int mb = 0; mb < 2; mb++) {
        const int m0 = bm + wr + mb * 16 + fr;
        const int m1 = m0 + 8;
        size_t ob0, ob1;
        if (EPI == EPI_SCATTER_RES) { ob0 = scatter_base(m0); ob1 = scatter_base(m1); }
        else                        { ob0 = (size_t)m0 * Nc;  ob1 = (size_t)m1 * Nc; }
        #pragma unroll
        for (int nb = 0; nb < 8; nb++) {
            const int n0 = bn + wc + nb * 8 + 2 * fc;
            float2 bb = *(const float2*)(bias + n0);
            float v0 = acc[mb][nb][0] + bb.x;
            float v1 = acc[mb][nb][1] + bb.y;
            float v2 = acc[mb][nb][2] + bb.x;
            float v3 = acc[mb][nb][3] + bb.y;
            if (EPI == EPI_GELU) {
                v0 = 0.5f * v0 * (1.0f + erff(v0 * 0.70710678118654752f));
                v1 = 0.5f * v1 * (1.0f + erff(v1 * 0.70710678118654752f));
                v2 = 0.5f * v2 * (1.0f + erff(v2 * 0.70710678118654752f));
                v3 = 0.5f * v3 * (1.0f + erff(v3 * 0.70710678118654752f));
            } else if (EPI == EPI_SCATTER_RES || EPI == EPI_RES) {
                float2 r0 = *(const float2*)(Res + ob0 + n0);
                float2 r1 = *(const float2*)(Res + ob1 + n0);
                v0 += r0.x; v1 += r0.y; v2 += r1.x; v3 += r1.y;
            }
            if (EPI == EPI_PLAIN || EPI == EPI_GELU) {
                *(uint32_t*)(outh + ob0 + n0) = pkh2(v0, v1);
                *(uint32_t*)(outh + ob1 + n0) = pkh2(v2, v3);
            } else {
                *(float2*)(outf + ob0 + n0) = make_float2(v0, v1);
                *(float2*)(outf + ob1 + n0) = make_float2(v2, v3);
            }
        }
    }
}

// ---------------- HMMA windowed attention ----------------------------------
#define BMS 68

__global__ __launch_bounds__(128)
void attn_mma(const __half* __restrict__ qkv,
              const float* __restrict__ bm,
              __half* __restrict__ outp)
{
    int head = blockIdx.x;
    int bw   = blockIdx.y;
    int wim  = bw & 63;
    int tid  = threadIdx.x;
    int lane = tid & 31;
    int w    = tid >> 5;
    int wr   = w * 16;

    __shared__ __half sQ[64*40], sK[64*40], sV[64*40];
    __shared__ float  sBM[64*BMS];

    size_t rowbase = (size_t)(bw * 64) * 1536 + head * 32;
    for (int i = tid; i < 256; i += 128) {
        int n = i >> 2, c = i & 3;
        const __half* src = qkv + rowbase + (size_t)n * 1536 + c * 8;
        *(uint4*)(sQ + n * 40 + c * 8) = *(const uint4*)src;
        *(uint4*)(sK + n * 40 + c * 8) = *(const uint4*)(src + 512);
        *(uint4*)(sV + n * 40 + c * 8) = *(const uint4*)(src + 1024);
    }
    {
        const float4* src = (const float4*)(bm + ((size_t)head * 64 + wim) * 4096);
        for (int e = tid; e < 1024; e += 128) {
            int n = e >> 4, c = e & 15;
            *(float4*)(sBM + n * BMS + c * 4) = src[e];
        }
    }
    __syncthreads();

    const uint32_t uQ = s2u(sQ), uK = s2u(sK), uV = s2u(sV);
    const int tile = lane >> 3, rit = lane & 7;
    const int fr = lane >> 2, fc = lane & 3;

    uint32_t aQ[2][4];
    #pragma unroll
    for (int kt = 0; kt < 2; kt++)
        LDSM4(aQ[kt], uQ + (uint32_t)(((wr + (tile & 1) * 8 + rit) * 40
                                       + (tile >> 1) * 8 + kt * 16) * 2));

    uint32_t bK[4][2][4];
    #pragma unroll
    for (int pt = 0; pt < 4; pt++)
        #pragma unroll
        for (int kt = 0; kt < 2; kt++)
            LDSM4(bK[pt][kt], uK + (uint32_t)(((pt * 16 + (tile >> 1) * 8 + rit) * 40
                                               + (tile & 1) * 8 + kt * 16) * 2));

    float c[8][4];
    #pragma unroll
    for (int i = 0; i < 8; i++)
        #pragma unroll
        for (int j = 0; j < 4; j++) c[i][j] = 0.f;
    #pragma unroll
    for (int pt = 0; pt < 4; pt++)
        #pragma unroll
        for (int kt = 0; kt < 2; kt++) {
            mma_f16(c[2 * pt],     aQ[kt], &bK[pt][kt][0]);
            mma_f16(c[2 * pt + 1], aQ[kt], &bK[pt][kt][2]);
        }

    const float* bm0 = sBM + (wr + fr) * BMS;
    const float* bm1 = bm0 + 8 * BMS;
    float mx0 = -1e30f, mx1 = -1e30f;
    #pragma unroll
    for (int nt = 0; nt < 8; nt++) {
        float2 b0 = *(const float2*)(bm0 + nt * 8 + 2 * fc);
        float2 b1 = *(const float2*)(bm1 + nt * 8 + 2 * fc);
        c[nt][0] = c[nt][0] * SCALE_F + b0.x;
        c[nt][1] = c[nt][1] * SCALE_F + b0.y;
        c[nt][2] = c[nt][2] * SCALE_F + b1.x;
        c[nt][3] = c[nt][3] * SCALE_F + b1.y;
        mx0 = fmaxf(mx0, fmaxf(c[nt][0], c[nt][1]));
        mx1 = fmaxf(mx1, fmaxf(c[nt][2], c[nt][3]));
    }
    mx0 = fmaxf(mx0, __shfl_xor_sync(0xffffffffu, mx0, 1));
    mx0 = fmaxf(mx0, __shfl_xor_sync(0xffffffffu, mx0, 2));
    mx1 = fmaxf(mx1, __shfl_xor_sync(0xffffffffu, mx1, 1));
    mx1 = fmaxf(mx1, __shfl_xor_sync(0xffffffffu, mx1, 2));

    float s0 = 0.f, s1 = 0.f;
    #pragma unroll
    for (int nt = 0; nt < 8; nt++) {
        c[nt][0] = __expf(c[nt][0] - mx0);
        c[nt][1] = __expf(c[nt][1] - mx0);
        c[nt][2] = __expf(c[nt][2] - mx1);
        c[nt][3] = __expf(c[nt][3] - mx1);
        s0 += c[nt][0] + c[nt][1];
        s1 += c[nt][2] + c[nt][3];
    }
    s0 += __shfl_xor_sync(0xffffffffu, s0, 1);
    s0 += __shfl_xor_sync(0xffffffffu, s0, 2);
    s1 += __shfl_xor_sync(0xffffffffu, s1, 1);
    s1 += __shfl_xor_sync(0xffffffffu, s1, 2);
    float i0 = 1.0f / s0, i1 = 1.0f / s1;

    uint32_t aP[4][4];
    #pragma unroll
    for (int kt = 0; kt < 4; kt++) {
        aP[kt][0] = pkh2(c[2*kt][0] * i0,   c[2*kt][1] * i0);
        aP[kt][1] = pkh2(c[2*kt][2] * i1,   c[2*kt][3] * i1);
        aP[kt][2] = pkh2(c[2*kt+1][0] * i0, c[2*kt+1][1] * i0);
        aP[kt][3] = pkh2(c[2*kt+1][2] * i1, c[2*kt+1][3] * i1);
    }

    float o[4][4];
    #pragma unroll
    for (int i = 0; i < 4; i++)
        #pragma unroll
        for (int j = 0; j < 4; j++) o[i][j] = 0.f;
    #pragma unroll
    for (int kt = 0; kt < 4; kt++)
        #pragma unroll
        for (int dh = 0; dh < 2; dh++) {
            uint32_t bV[4];
            LDSM4T(bV, uV + (uint32_t)(((kt * 16 + ((lane >> 3) & 1) * 8 + (lane & 7)) * 40
                                        + (lane >> 4) * 8 + dh * 16) * 2));
            mma_f16(o[2 * dh],     aP[kt], &bV[0]);
            mma_f16(o[2 * dh + 1], aP[kt], &bV[2]);
        }

    size_t orow = (size_t)(bw * 64 + wr + fr) * 512 + head * 32;
    #pragma unroll
    for (int nt = 0; nt < 4; nt++) {
        *(uint32_t*)(outp + orow + nt * 8 + 2 * fc)             = pkh2(o[nt][0], o[nt][1]);
        *(uint32_t*)(outp + orow + 8 * 512 + nt * 8 + 2 * fc)   = pkh2(o[nt][2], o[nt][3]);
    }
}

// ---------------- launch ----------------
extern "C" void kernel_launch(void* const* d_in, const int* in_sizes, int n_in,
                              void* d_out, int out_size)
{
    const float* x      = (const float*)d_in[0];
    const float* qkv_w  = (const float*)d_in[1];
    const float* qkv_b  = (const float*)d_in[2];
    const float* proj_w = (const float*)d_in[3];
    const float* proj_b = (const float*)d_in[4];
    const float* n1w    = (const float*)d_in[5];
    const float* n1b    = (const float*)d_in[6];
    const float* n2w    = (const float*)d_in[7];
    const float* n2b    = (const float*)d_in[8];
    const float* fc1w   = (const float*)d_in[9];
    const float* fc1b   = (const float*)d_in[10];
    const float* fc2w   = (const float*)d_in[11];
    const float* fc2b   = (const float*)d_in[12];
    const float* rbt    = (const float*)d_in[13];
    const int*   rpi    = (const int*)d_in[14];
    const float* amask  = (const float*)d_in[15];
    float*       out    = (float*)d_out;

    __half *hwin, *qkvb, *ob, *h2nb, *hidb, *wq, *wp, *w1, *w2;
    float *x1b, *bmb;
    cudaGetSymbolAddress((void**)&hwin, g_hwin);
    cudaGetSymbolAddress((void**)&qkvb, g_qkv);
    cudaGetSymbolAddress((void**)&ob,   g_o);
    cudaGetSymbolAddress((void**)&x1b,  g_x1);
    cudaGetSymbolAddress((void**)&h2nb, g_h2n);
    cudaGetSymbolAddress((void**)&hidb, g_hid);
    cudaGetSymbolAddress((void**)&wq,   g_wq);
    cudaGetSymbolAddress((void**)&wp,   g_wp);
    cudaGetSymbolAddress((void**)&w1,   g_w1);
    cudaGetSymbolAddress((void**)&w2,   g_w2);
    cudaGetSymbolAddress((void**)&bmb,  g_bm);

    cudaFuncSetAttribute(h_gemm<EPI_PLAIN>,       cudaFuncAttributeMaxDynamicSharedMemorySize, HSM_TOTAL);
    cudaFuncSetAttribute(h_gemm<EPI_GELU>,        cudaFuncAttributeMaxDynamicSharedMemorySize, HSM_TOTAL);
    cudaFuncSetAttribute(h_gemm<EPI_SCATTER_RES>, cudaFuncAttributeMaxDynamicSharedMemorySize, HSM_TOTAL);
    cudaFuncSetAttribute(h_gemm<EPI_RES>,         cudaFuncAttributeMaxDynamicSharedMemorySize, HSM_TOTAL);

    cvtw_all<<<786432/256, 256>>>(qkv_w, proj_w, fc1w, fc2w, wq, wp, w1, w2);
    bmprep<<<1024, 256>>>(amask, rbt, rpi, bmb);

    ln_kernel<true><<<MTOK, 128>>>(x, n1w, n1b, hwin);

    h_gemm<EPI_PLAIN><<<dim3(1536/128, MTOK/128), 256, HSM_TOTAL>>>(
        hwin, wq, qkv_b, nullptr, qkvb, 1536, 512, nullptr);

    attn_mma<<<dim3(HEADS, BB*64), 128>>>(qkvb, bmb, ob);

    h_gemm<EPI_SCATTER_RES><<<dim3(512/128, MTOK/128), 256, HSM_TOTAL>>>(
        ob, wp, proj_b, x1b, nullptr, 512, 512, x);

    ln_kernel<false><<<MTOK, 128>>>(x1b, n2w, n2b, h2nb);

    h_gemm<EPI_GELU><<<dim3(2048/128, MTOK/128), 256, HSM_TOTAL>>>(
        h2nb, w1, fc1b, nullptr, hidb, 2048, 512, nullptr);

    h_gemm<EPI_RES><<<dim3(512/128, MTOK/128), 256, HSM_TOTAL>>>(
        hidb, w2, fc2b, out, nullptr, 512, 2048, x1b);
}

// round 16
// speedup vs baseline: 1.1326x; 1.0265x over previous
#include <cuda_runtime.h>
#include <cuda_fp16.h>
#include <math.h>
#include <stdint.h>

// ---------------- static config ----------------
#define BB      16
#define CC      512
#define HEADS   16
#define SHIFT   4
#define HID     2048
#define MTOK    (BB*64*64)   // 65536
#define SCALE_F 0.17677669529663687f
#define EPSF    1e-5f

// ---------------- scratch ----------------
__device__ __half g_hwin[(size_t)MTOK * CC];
__device__ __half g_qkv [(size_t)MTOK * 3 * CC];
__device__ __half g_o   [(size_t)MTOK * CC];
__device__ float  g_x1  [(size_t)MTOK * CC];
__device__ __half g_h2n [(size_t)MTOK * CC];
__device__ __half g_hid [(size_t)MTOK * HID];
__device__ __half g_wq  [3*CC*CC];
__device__ __half g_wp  [CC*CC];
__device__ __half g_w1  [HID*CC];
__device__ __half g_w2  [CC*HID];
__device__ float  g_bm  [(size_t)1024 * 4096];

// ---------------- helpers ----------------
__device__ __forceinline__ uint32_t s2u(const void* p) {
    uint32_t a;
    asm("{ .reg .u64 t; cvta.to.shared.u64 t, %1; cvt.u32.u64 %0, t; }" : "=r"(a) : "l"(p));
    return a;
}
#define CP16(s, g) \
    asm volatile("cp.async.cg.shared.global [%0], [%1], 16;" :: "r"(s), "l"(g))
#define CP_COMMIT() asm volatile("cp.async.commit_group;" ::: "memory")
#define CP_WAIT(N)  asm volatile("cp.async.wait_group %0;" :: "n"(N) : "memory")

#define LDSM4(r, a) \
    asm volatile("ldmatrix.sync.aligned.m8n8.x4.shared.b16 {%0,%1,%2,%3}, [%4];" \
        : "=r"((r)[0]), "=r"((r)[1]), "=r"((r)[2]), "=r"((r)[3]) : "r"(a))
#define LDSM4T(r, a) \
    asm volatile("ldmatrix.sync.aligned.m8n8.x4.trans.shared.b16 {%0,%1,%2,%3}, [%4];" \
        : "=r"((r)[0]), "=r"((r)[1]), "=r"((r)[2]), "=r"((r)[3]) : "r"(a))

__device__ __forceinline__ void mma_f16(float* c, const uint32_t* a, const uint32_t* b) {
    asm volatile(
        "mma.sync.aligned.m16n8k16.row.col.f32.f16.f16.f32 "
        "{%0,%1,%2,%3}, {%4,%5,%6,%7}, {%8,%9}, {%0,%1,%2,%3};"
        : "+f"(c[0]), "+f"(c[1]), "+f"(c[2]), "+f"(c[3])
        : "r"(a[0]), "r"(a[1]), "r"(a[2]), "r"(a[3]), "r"(b[0]), "r"(b[1]));
}

__device__ __forceinline__ uint32_t pkh2(float a, float b) {
    __half2 t = __floats2half2_rn(a, b);
    return *reinterpret_cast<uint32_t*>(&t);
}

__device__ __forceinline__ size_t scatter_base(int m) {
    int bb = m >> 12, rem = m & 4095;
    int wdx = rem >> 6, n = rem & 63;
    int wh = wdx >> 3, ww = wdx & 7;
    int r = n >> 3, s = n & 7;
    int hp = ((wh << 3) + r + SHIFT) & 63;
    int wp = ((ww << 3) + s + SHIFT) & 63;
    return ((size_t)bb * 4096 + hp * 64 + wp) * CC;
}

// ---------------- fused weight conversion fp32 -> fp16 ----------------
__global__ void cvtw_all(const float* __restrict__ qkv_w, const float* __restrict__ proj_w,
                         const float* __restrict__ fc1_w, const float* __restrict__ fc2_w,
                         __half* __restrict__ wq, __half* __restrict__ wp,
                         __half* __restrict__ w1, __half* __restrict__ w2)
{
    int i = blockIdx.x * 256 + threadIdx.x;
    const float* src; __half* dst; int off;
    if (i < 196608)       { src = qkv_w;  dst = wq; off = i; }
    else if (i < 262144)  { src = proj_w; dst = wp; off = i - 196608; }
    else if (i < 524288)  { src = fc1_w;  dst = w1; off = i - 262144; }
    else                  { src = fc2_w;  dst = w2; off = i - 524288; }
    float4 v = ((const float4*)src)[off];
    __half2 a = __floats2half2_rn(v.x, v.y);
    __half2 b = __floats2half2_rn(v.z, v.w);
    uint2 pk = { *(uint32_t*)&a, *(uint32_t*)&b };
    ((uint2*)dst)[off] = pk;
}

// ---------------- bias+mask precompute ----------------
__global__ void bmprep(const float* __restrict__ mask,
                       const float* __restrict__ rbt,
                       const int*   __restrict__ rpi,
                       float* __restrict__ bm)
{
    int hw   = blockIdx.x;
    int head = hw >> 6, wim = hw & 63;
    const float* mrow = mask + wim * 4096;
    float* dst = bm + (size_t)hw * 4096;
    for (int e = threadIdx.x; e < 4096; e += 256)
        dst[e] = mrow[e] + rbt[rpi[e] * HEADS + head];
}

// ---------------- LayerNorm (+shift/window gather), fp16 out ---------------
template<bool SHIFTED>
__global__ void ln_kernel(const float* __restrict__ x,
                          const float* __restrict__ w,
                          const float* __restrict__ b,
                          __half* __restrict__ out)
{
    __shared__ float sh[4];
    int m   = blockIdx.x;
    int tid = threadIdx.x;          // 128

    size_t dst_row = (size_t)m * CC;
    size_t src_row = dst_row;
    if (SHIFTED) {
        int bb  = m >> 12;
        int rem = m & 4095;
        int wdx = rem >> 6, n = rem & 63;
        int wh = wdx >> 3, ww = wdx & 7;
        int r  = n >> 3, s = n & 7;
        int shp = ((wh << 3) + r + SHIFT) & 63;
        int swp = ((ww << 3) + s + SHIFT) & 63;
        src_row = ((size_t)bb * 4096 + shp * 64 + swp) * CC;
    }

    float4 v = ((const float4*)(x + src_row))[tid];

    float sum = v.x + v.y + v.z + v.w;
    #pragma unroll
    for (int o = 16; o > 0; o >>= 1) sum += __shfl_xor_sync(0xffffffffu, sum, o);
    if ((tid & 31) == 0) sh[tid >> 5] = sum;
    __syncthreads();
    float mean = (sh[0] + sh[1] + sh[2] + sh[3]) * (1.0f / CC);
    __syncthreads();

    float d0 = v.x - mean, d1 = v.y - mean, d2 = v.z - mean, d3 = v.w - mean;
    float sq = d0*d0 + d1*d1 + d2*d2 + d3*d3;
    #pragma unroll
    for (int o = 16; o > 0; o >>= 1) sq += __shfl_xor_sync(0xffffffffu, sq, o);
    if ((tid & 31) == 0) sh[tid >> 5] = sq;
    __syncthreads();
    float var = (sh[0] + sh[1] + sh[2] + sh[3]) * (1.0f / CC);
    float inv = rsqrtf(var + EPSF);

    float4 w4 = ((const float4*)w)[tid];
    float4 b4 = ((const float4*)b)[tid];
    __half2 h01 = __floats2half2_rn(d0 * inv * w4.x + b4.x, d1 * inv * w4.y + b4.y);
    __half2 h23 = __floats2half2_rn(d2 * inv * w4.z + b4.z, d3 * inv * w4.w + b4.w);
    uint2 pk = { *(uint32_t*)&h01, *(uint32_t*)&h23 };
    *(uint2*)(out + dst_row + tid * 4) = pk;
}

// ---------------- fp16 HMMA GEMM, 256 thr, 128x128 block, 32x64 warp tile --
// 4-stage ring, processed in chunk PAIRS (unchanged from R15 winner)
#define EPI_PLAIN       0
#define EPI_GELU        1
#define EPI_SCATTER_RES 2
#define EPI_RES         3

#define HSTAGE    20480
#define HSM_TOTAL 81920   // 4 stages

__device__ __forceinline__ void cp_chunk(uint32_t sb, int buf, int tid,
                                         const __half* pa, const __half* pb) {
    const int row = tid >> 1, hf = tid & 1;
    uint32_t da = sb + buf * HSTAGE +         row * 80 + hf * 32;
    uint32_t db = sb + buf * HSTAGE + 10240 + row * 80 + hf * 32;
    CP16(da,      pa);
    CP16(da + 16, pa + 8);
    CP16(db,      pb);
    CP16(db + 16, pb + 8);
}

template<int EPI>
__global__ __launch_bounds__(256, 2)
void h_gemm(const __half* __restrict__ A,
            const __half* __restrict__ Bw,
            const float* __restrict__ bias,
            float* __restrict__ outf,
            __half* __restrict__ outh,
            int Nc, int K,
            const float* __restrict__ Res)
{
    extern __shared__ char smem[];

    const int tid  = threadIdx.x;     // 256
    const int lane = tid & 31;
    const int w    = tid >> 5;        // 8 warps
    const int wr   = (w >> 1) * 32;
    const int wc   = (w & 1)  * 64;
    const int bm   = blockIdx.y * 128;
    const int bn   = blockIdx.x * 128;

    const uint32_t sb = s2u(smem);

    const int lrow = tid >> 1, lhf = tid & 1;
    const __half* gA = A  + (size_t)(bm + lrow) * K + lhf * 16;
    const __half* gB = Bw + (size_t)(bn + lrow) * K + lhf * 16;

    float acc[2][8][4];
    #pragma unroll
    for (int i = 0; i < 2; i++)
        #pragma unroll
        for (int j = 0; j < 8; j++)
            #pragma unroll
            for (int q = 0; q < 4; q++) acc[i][j][q] = 0.f;

    const int npair = K >> 6;

    const int tile = lane >> 3, rit = lane & 7;
    uint32_t aOff[2], bOff[4];
    #pragma unroll
    for (int mb = 0; mb < 2; mb++)
        aOff[mb] = (uint32_t)((wr + mb * 16 + (tile & 1) * 8 + rit) * 80 + (tile >> 1) * 16);
    #pragma unroll
    for (int p = 0; p < 4; p++)
        bOff[p] = (uint32_t)(10240 + (wc + p * 16 + (tile >> 1) * 8 + rit) * 80 + (tile & 1) * 16);

    cp_chunk(sb, 0, tid, gA,      gB);
    cp_chunk(sb, 1, tid, gA + 32, gB + 32);
    CP_COMMIT();

    for (int p = 0; p < npair; p++) {
        CP_WAIT(0);
        __syncthreads();
        const int pb2 = (p & 1) * 2;
        if (p + 1 < npair) {
            const int nb2 = ((p + 1) & 1) * 2;
            const __half* pa = gA + (size_t)(p + 1) * 64;
            const __half* pbp = gB + (size_t)(p + 1) * 64;
            cp_chunk(sb, nb2,     tid, pa,      pbp);
            cp_chunk(sb, nb2 + 1, tid, pa + 32, pbp + 32);
            CP_COMMIT();
        }
        #pragma unroll
        for (int sub = 0; sub < 2; sub++) {
            const uint32_t stb = sb + (uint32_t)(pb2 + sub) * HSTAGE;
            #pragma unroll
            for (int kk = 0; kk < 2; kk++) {
                uint32_t a[2][4], b[4][4];
                #pragma unroll
                for (int mb = 0; mb < 2; mb++) LDSM4(a[mb], stb + aOff[mb] + kk * 32);
                #pragma unroll
                for (int pt = 0; pt < 4; pt++) LDSM4(b[pt], stb + bOff[pt] + kk * 32);
                #pragma unroll
                for (int mb = 0; mb < 2; mb++)
                    #pragma unroll
                    for (int nb = 0; nb < 8; nb++)
                        mma_f16(acc[mb][nb], a[mb], &b[nb >> 1][(nb & 1) * 2]);
            }
        }
    }

    const int fr = lane >> 2, fc = lane & 3;
    #pragma unroll
    for (int mb = 0; mb < 2; mb++) {
        const int m0 = bm + wr + mb * 16 + fr;
        const int m1 = m0 + 8;
        size_t ob0, ob1;
        if (EPI == EPI_SCATTER_RES) { ob0 = scatter_base(m0); ob1 = scatter_base(m1); }
        else                        { ob0 = (size_t)m0 * Nc;  ob1 = (size_t)m1 * Nc; }
        #pragma unroll
        for (int nb = 0; nb < 8; nb++) {
            const int n0 = bn + wc + nb * 8 + 2 * fc;
            float2 bb = *(const float2*)(bias + n0);
            float v0 = acc[mb][nb][0] + bb.x;
            float v1 = acc[mb][nb][1] + bb.y;
            float v2 = acc[mb][nb][2] + bb.x;
            float v3 = acc[mb][nb][3] + bb.y;
            if (EPI == EPI_GELU) {
                v0 = 0.5f * v0 * (1.0f + erff(v0 * 0.70710678118654752f));
                v1 = 0.5f * v1 * (1.0f + erff(v1 * 0.70710678118654752f));
                v2 = 0.5f * v2 * (1.0f + erff(v2 * 0.70710678118654752f));
                v3 = 0.5f * v3 * (1.0f + erff(v3 * 0.70710678118654752f));
            } else if (EPI == EPI_SCATTER_RES || EPI == EPI_RES) {
                float2 r0 = *(const float2*)(Res + ob0 + n0);
                float2 r1 = *(const float2*)(Res + ob1 + n0);
                v0 += r0.x; v1 += r0.y; v2 += r1.x; v3 += r1.y;
            }
            if (EPI == EPI_PLAIN || EPI == EPI_GELU) {
                *(uint32_t*)(outh + ob0 + n0) = pkh2(v0, v1);
                *(uint32_t*)(outh + ob1 + n0) = pkh2(v2, v3);
            } else {
                *(float2*)(outf + ob0 + n0) = make_float2(v0, v1);
                *(float2*)(outf + ob1 + n0) = make_float2(v2, v3);
            }
        }
    }
}

// ---------------- HMMA windowed attention, batched per (head,window) -------
// block = (head, wim); loops over 16 batch images, sBM loaded ONCE.
// QKV double-buffered via cp.async. smem: 2*3*2560*2B + 64*68*4B = 48,128 B
#define BMS 68

__global__ __launch_bounds__(128)
void attn_mma(const __half* __restrict__ qkv,
              const float* __restrict__ bm,
              __half* __restrict__ outp)
{
    int head = blockIdx.x;          // 0..15
    int wim  = blockIdx.y;          // 0..63
    int tid  = threadIdx.x;
    int lane = tid & 31;
    int w    = tid >> 5;
    int wr   = w * 16;

    __shared__ __half sQ[2][64*40], sK[2][64*40], sV[2][64*40];
    __shared__ float  sBM[64*BMS];

    const uint32_t uQ[2] = { s2u(sQ[0]), s2u(sQ[1]) };
    const uint32_t uK[2] = { s2u(sK[0]), s2u(sK[1]) };
    const uint32_t uV[2] = { s2u(sV[0]), s2u(sV[1]) };

    // bias+mask once
    {
        const float4* src = (const float4*)(bm + ((size_t)head * 64 + wim) * 4096);
        for (int e = tid; e < 1024; e += 128) {
            int n = e >> 4, c = e & 15;
            *(float4*)(sBM + n * BMS + c * 4) = src[e];
        }
    }

    // async QKV loader for batch b into buffer buf
    auto load_b = [&](int b, int buf) {
        size_t rowbase = (size_t)((b * 64 + wim) * 64) * 1536 + head * 32;
        #pragma unroll
        for (int it = 0; it < 2; it++) {
            int i = tid + it * 128;
            int n = i >> 2, c = i & 3;
            const __half* src = qkv + rowbase + (size_t)n * 1536 + c * 8;
            uint32_t off = (uint32_t)(n * 80 + c * 16);
            CP16(uQ[buf] + off, src);
            CP16(uK[buf] + off, src + 512);
            CP16(uV[buf] + off, src + 1024);
        }
        CP_COMMIT();
    };

    load_b(0, 0);

    const int tile = lane >> 3, rit = lane & 7;
    const int fr = lane >> 2, fc = lane & 3;

    uint32_t aQoff[2], bKoff[4][2], bVoff[4][2];
    #pragma unroll
    for (int kt = 0; kt < 2; kt++)
        aQoff[kt] = (uint32_t)(((wr + (tile & 1) * 8 + rit) * 40
                                + (tile >> 1) * 8 + kt * 16) * 2);
    #pragma unroll
    for (int pt = 0; pt < 4; pt++)
        #pragma unroll
        for (int kt = 0; kt < 2; kt++)
            bKoff[pt][kt] = (uint32_t)(((pt * 16 + (tile >> 1) * 8 + rit) * 40
                                        + (tile & 1) * 8 + kt * 16) * 2);
    #pragma unroll
    for (int kt = 0; kt < 4; kt++)
        #pragma unroll
        for (int dh = 0; dh < 2; dh++)
            bVoff[kt][dh] = (uint32_t)(((kt * 16 + ((lane >> 3) & 1) * 8 + (lane & 7)) * 40
                                        + (lane >> 4) * 8 + dh * 16) * 2);

    const float* bm0 = sBM + (wr + fr) * BMS;
    const float* bm1 = bm0 + 8 * BMS;

    for (int b = 0; b < BB; b++) {
        const int buf = b & 1;
        CP_WAIT(0);
        __syncthreads();
        if (b + 1 < BB) load_b(b + 1, buf ^ 1);

        uint32_t aQ[2][4];
        #pragma unroll
        for (int kt = 0; kt < 2; kt++) LDSM4(aQ[kt], uQ[buf] + aQoff[kt]);

        uint32_t bK[4][2][4];
        #pragma unroll
        for (int pt = 0; pt < 4; pt++)
            #pragma unroll
            for (int kt = 0; kt < 2; kt++)
                LDSM4(bK[pt][kt], uK[buf] + bKoff[pt][kt]);

        float c[8][4];
        #pragma unroll
        for (int i = 0; i < 8; i++)
            #pragma unroll
            for (int j = 0; j < 4; j++) c[i][j] = 0.f;
        #pragma unroll
        for (int pt = 0; pt < 4; pt++)
            #pragma unroll
            for (int kt = 0; kt < 2; kt++) {
                mma_f16(c[2 * pt],     aQ[kt], &bK[pt][kt][0]);
                mma_f16(c[2 * pt + 1], aQ[kt], &bK[pt][kt][2]);
            }

        float mx0 = -1e30f, mx1 = -1e30f;
        #pragma unroll
        for (int nt = 0; nt < 8; nt++) {
            float2 b0 = *(const float2*)(bm0 + nt * 8 + 2 * fc);
            float2 b1 = *(const float2*)(bm1 + nt * 8 + 2 * fc);
            c[nt][0] = c[nt][0] * SCALE_F + b0.x;
            c[nt][1] = c[nt][1] * SCALE_F + b0.y;
            c[nt][2] = c[nt][2] * SCALE_F + b1.x;
            c[nt][3] = c[nt][3] * SCALE_F + b1.y;
            mx0 = fmaxf(mx0, fmaxf(c[nt][0], c[nt][1]));
            mx1 = fmaxf(mx1, fmaxf(c[nt][2], c[nt][3]));
        }
        mx0 = fmaxf(mx0, __shfl_xor_sync(0xffffffffu, mx0, 1));
        mx0 = fmaxf(mx0, __shfl_xor_sync(0xffffffffu, mx0, 2));
        mx1 = fmaxf(mx1, __shfl_xor_sync(0xffffffffu, mx1, 1));
        mx1 = fmaxf(mx1, __shfl_xor_sync(0xffffffffu, mx1, 2));

        float s0 = 0.f, s1 = 0.f;
        #pragma unroll
        for (int nt = 0; nt < 8; nt++) {
            c[nt][0] = __expf(c[nt][0] - mx0);
            c[nt][1] = __expf(c[nt][1] - mx0);
            c[nt][2] = __expf(c[nt][2] - mx1);
            c[nt][3] = __expf(c[nt][3] - mx1);
            s0 += c[nt][0] + c[nt][1];
            s1 += c[nt][2] + c[nt][3];
        }
        s0 += __shfl_xor_sync(0xffffffffu, s0, 1);
        s0 += __shfl_xor_sync(0xffffffffu, s0, 2);
        s1 += __shfl_xor_sync(0xffffffffu, s1, 1);
        s1 += __shfl_xor_sync(0xffffffffu, s1, 2);
        float i0 = 1.0f / s0, i1 = 1.0f / s1;

        uint32_t aP[4][4];
        #pragma unroll
        for (int kt = 0; kt < 4; kt++) {
            aP[kt][0] = pkh2(c[2*kt][0] * i0,   c[2*kt][1] * i0);
            aP[kt][1] = pkh2(c[2*kt][2] * i1,   c[2*kt][3] * i1);
            aP[kt][2] = pkh2(c[2*kt+1][0] * i0, c[2*kt+1][1] * i0);
            aP[kt][3] = pkh2(c[2*kt+1][2] * i1, c[2*kt+1][3] * i1);
        }

        float o[4][4];
        #pragma unroll
        for (int i = 0; i < 4; i++)
            #pragma unroll
            for (int j = 0; j < 4; j++) o[i][j] = 0.f;
        #pragma unroll
        for (int kt = 0; kt < 4; kt++)
            #pragma unroll
            for (int dh = 0; dh < 2; dh++) {
                uint32_t bV[4];
                LDSM4T(bV, uV[buf] + bVoff[kt][dh]);
                mma_f16(o[2 * dh],     aP[kt], &bV[0]);
                mma_f16(o[2 * dh + 1], aP[kt], &bV[2]);
            }

        size_t orow = (size_t)((b * 64 + wim) * 64 + wr + fr) * 512 + head * 32;
        #pragma unroll
        for (int nt = 0; nt < 4; nt++) {
            *(uint32_t*)(outp + orow + nt * 8 + 2 * fc)           = pkh2(o[nt][0], o[nt][1]);
            *(uint32_t*)(outp + orow + 8 * 512 + nt * 8 + 2 * fc) = pkh2(o[nt][2], o[nt][3]);
        }
    }
}

// ---------------- launch ----------------
extern "C" void kernel_launch(void* const* d_in, const int* in_sizes, int n_in,
                              void* d_out, int out_size)
{
    const float* x      = (const float*)d_in[0];
    const float* qkv_w  = (const float*)d_in[1];
    const float* qkv_b  = (const float*)d_in[2];
    const float* proj_w = (const float*)d_in[3];
    const float* proj_b = (const float*)d_in[4];
    const float* n1w    = (const float*)d_in[5];
    const float* n1b    = (const float*)d_in[6];
    const float* n2w    = (const float*)d_in[7];
    const float* n2b    = (const float*)d_in[8];
    const float* fc1w   = (const float*)d_in[9];
    const float* fc1b   = (const float*)d_in[10];
    const float* fc2w   = (const float*)d_in[11];
    const float* fc2b   = (const float*)d_in[12];
    const float* rbt    = (const float*)d_in[13];
    const int*   rpi    = (const int*)d_in[14];
    const float* amask  = (const float*)d_in[15];
    float*       out    = (float*)d_out;

    __half *hwin, *qkvb, *ob, *h2nb, *hidb, *wq, *wp, *w1, *w2;
    float *x1b, *bmb;
    cudaGetSymbolAddress((void**)&hwin, g_hwin);
    cudaGetSymbolAddress((void**)&qkvb, g_qkv);
    cudaGetSymbolAddress((void**)&ob,   g_o);
    cudaGetSymbolAddress((void**)&x1b,  g_x1);
    cudaGetSymbolAddress((void**)&h2nb, g_h2n);
    cudaGetSymbolAddress((void**)&hidb, g_hid);
    cudaGetSymbolAddress((void**)&wq,   g_wq);
    cudaGetSymbolAddress((void**)&wp,   g_wp);
    cudaGetSymbolAddress((void**)&w1,   g_w1);
    cudaGetSymbolAddress((void**)&w2,   g_w2);
    cudaGetSymbolAddress((void**)&bmb,  g_bm);

    cudaFuncSetAttribute(h_gemm<EPI_PLAIN>,       cudaFuncAttributeMaxDynamicSharedMemorySize, HSM_TOTAL);
    cudaFuncSetAttribute(h_gemm<EPI_GELU>,        cudaFuncAttributeMaxDynamicSharedMemorySize, HSM_TOTAL);
    cudaFuncSetAttribute(h_gemm<EPI_SCATTER_RES>, cudaFuncAttributeMaxDynamicSharedMemorySize, HSM_TOTAL);
    cudaFuncSetAttribute(h_gemm<EPI_RES>,         cudaFuncAttributeMaxDynamicSharedMemorySize, HSM_TOTAL);

    cvtw_all<<<786432/256, 256>>>(qkv_w, proj_w, fc1w, fc2w, wq, wp, w1, w2);
    bmprep<<<1024, 256>>>(amask, rbt, rpi, bmb);

    ln_kernel<true><<<MTOK, 128>>>(x, n1w, n1b, hwin);

    h_gemm<EPI_PLAIN><<<dim3(1536/128, MTOK/128), 256, HSM_TOTAL>>>(
        hwin, wq, qkv_b, nullptr, qkvb, 1536, 512, nullptr);

    attn_mma<<<dim3(HEADS, 64), 128>>>(qkvb, bmb, ob);

    h_gemm<EPI_SCATTER_RES><<<dim3(512/128, MTOK/128), 256, HSM_TOTAL>>>(
        ob, wp, proj_b, x1b, nullptr, 512, 512, x);

    ln_kernel<false><<<MTOK, 128>>>(x1b, n2w, n2b, h2nb);

    h_gemm<EPI_GELU><<<dim3(2048/128, MTOK/128), 256, HSM_TOTAL>>>(
        h2nb, w1, fc1b, nullptr, hidb, 2048, 512, nullptr);

    h_gemm<EPI_RES><<<dim3(512/128, MTOK/128), 256, HSM_TOTAL>>>(
        hidb, w2, fc2b, out, nullptr, 512, 2048, x1b);
}